// round 8
// baseline (speedup 1.0000x reference)
#include <cuda_runtime.h>

#define THREADS 256
#define TT 30
#define RS 68   // per-k stride for dup-state arrays (64 dup floats + pad)

typedef unsigned long long ull;

// ---------------- shared memory layout (float offsets) ----------------
#define WT     0        // P1: W1' [80][256]=20480 ; P2: W3' [32][128]=4096
#define W2o    20480    // P1: W2' [96][128]=12288
#define W4o    4096     // P2: W4' [96][256]=24576
#define WOUTo  28672    // P2: Wout' [64][16]=1024
#define WIH3o  29696    // P2: Wih3' [32][128]=4096   (ends 33792)
#define B1o    33792    // 256   (interleaved [u][g])
#define B2o    34048    // 128
#define B3o    34176    // 128
#define B4o    34304    // 256
#define BOo    34560    // 16
// dup state: [k][dup-row], stride RS; row r at offset 2r + 4*(r>=16)
#define XINo   34576    // 2 x [16][68] = 2176
#define H1o    36752    // 2 x [64][68] = 8704   (P2: h4)
#define H2o    45456    // 2 x [32][68] = 4352   (P2: h3)
#define SHF    49808    // 199232 bytes

__device__ __forceinline__ void ffma2(ull &acc, ull a, ull b){
    asm("fma.rn.f32x2 %0, %1, %2, %0;" : "+l"(acc) : "l"(a), "l"(b));
}
__device__ __forceinline__ ull pack2(float x, float y){
    ull r; asm("mov.b64 %0, {%1, %2};" : "=l"(r) : "f"(x), "f"(y)); return r;
}
__device__ __forceinline__ float2 unpack2(ull v){
    float2 f; asm("mov.b64 {%0, %1}, %2;" : "=f"(f.x), "=f"(f.y) : "l"(v)); return f;
}
__device__ __forceinline__ float ex2x(float x){
    float e; asm("ex2.approx.f32 %0, %1;" : "=f"(e) : "f"(x)); return e;
}
__device__ __forceinline__ float rcpx(float x){
    float r; asm("rcp.approx.f32 %0, %1;" : "=f"(r) : "f"(x)); return r;
}

// 8-MUFU LSTM activation (gate order i,f,g,o). Returns h, updates c.
__device__ __forceinline__ float act8(float zi, float zf, float zg, float zo, float &c){
    const float K1 = -1.4426950408889634f;
    float ei = ex2x(K1 * zi);
    float ef = ex2x(K1 * zf);
    float eg = ex2x(2.0f * K1 * zg);
    float eo = ex2x(K1 * zo);
    float A = 1.0f + ei, F = 1.0f + ef, G = 1.0f + eg, O = 1.0f + eo;
    float it = (1.0f - eg) * rcpx(A * G);
    float cn = fmaf(c, rcpx(F), it);
    float ec = ex2x(2.0f * K1 * cn);
    float C = 1.0f + ec;
    c = cn;
    return (1.0f - ec) * rcpx(O * C);
}

// acc[j][gp][r]: unit u0+j, gate-pair gp (0:(i,f), 1:(g,o)), row r0+r.
// Weights packed gate-pairs (direct LDS.128); input dup pairs (direct LDS.128).
// in: dup array [k][drow]; W pre-offset by u0*4; doff0 = dup offset of r0.
template<int NU, int NG>
__device__ __forceinline__ void accum(const float* __restrict__ in,
                                      const float* __restrict__ W,
                                      int K, ull (&acc)[NU][2][4], int doff0)
{
#pragma unroll 4
    for (int k = 0; k < K; k++) {
        ulonglong2 hA = *reinterpret_cast<const ulonglong2*>(in + k*RS + doff0);     // rows r0,r0+1
        ulonglong2 hB = *reinterpret_cast<const ulonglong2*>(in + k*RS + doff0 + 4); // rows r0+2,r0+3
#pragma unroll
        for (int j = 0; j < NU; j++) {
            ulonglong2 wv = *reinterpret_cast<const ulonglong2*>(W + k*NG + j*4);
            ffma2(acc[j][0][0], wv.x, hA.x); ffma2(acc[j][0][1], wv.x, hA.y);
            ffma2(acc[j][0][2], wv.x, hB.x); ffma2(acc[j][0][3], wv.x, hB.y);
            ffma2(acc[j][1][0], wv.y, hA.x); ffma2(acc[j][1][1], wv.y, hA.y);
            ffma2(acc[j][1][2], wv.y, hB.x); ffma2(acc[j][1][3], wv.y, hB.y);
        }
    }
}

template<int NU>
__device__ __forceinline__ void init_acc(ull (&acc)[NU][2][4], const ull (&b)[NU][2]){
#pragma unroll
    for (int j = 0; j < NU; j++)
#pragma unroll
        for (int g = 0; g < 2; g++)
#pragma unroll
            for (int p = 0; p < 4; p++) acc[j][g][p] = b[j][g];
}

// activation; writes h as dup pairs. hdst pre-offset by u0*RS.
template<int NU>
__device__ __forceinline__ void act_store(ull (&acc)[NU][2][4], float (&c)[NU][4],
                                          float* hdst, int doff0)
{
#pragma unroll
    for (int j = 0; j < NU; j++)
#pragma unroll
    for (int r = 0; r < 4; r++) {
        float2 zif = unpack2(acc[j][0][r]);
        float2 zgo = unpack2(acc[j][1][r]);
        float h = act8(zif.x, zif.y, zgo.x, zgo.y, c[j][r]);
        *reinterpret_cast<ull*>(hdst + j*RS + doff0 + 2*r) = pack2(h, h);
    }
}

__global__ void __launch_bounds__(THREADS, 1)
lstm_ae(const float* __restrict__ x,
        const float* __restrict__ Wih1, const float* __restrict__ Whh1, const float* __restrict__ b1,
        const float* __restrict__ Wih2, const float* __restrict__ Whh2, const float* __restrict__ b2,
        const float* __restrict__ Wih3, const float* __restrict__ Whh3, const float* __restrict__ b3,
        const float* __restrict__ Wih4, const float* __restrict__ Whh4, const float* __restrict__ b4,
        const float* __restrict__ Wout, const float* __restrict__ bout,
        float* __restrict__ out)
{
    extern __shared__ float sh[];
    const int tid = threadIdx.x;
    const int wid = tid >> 5;
    const bool grpA = ((wid >> 2) & 1) == 0;
    const long row0 = (long)blockIdx.x * 32;

    const int ug  = tid >> 3;                  // 0..31
    const int u0a = ug * 2;                    // H=64 layers: 2 units
    const int u0b = ug;                        // H=32 layers: 1 unit
    const int r0  = (tid & 7) * 4;             // 4 rows
    const int doff0 = 2 * r0 + ((r0 & 16) >> 2);

    // x / proj per-thread mapping: one row + 2 features
    const int xr  = tid >> 3;                  // row 0..31
    const int xf0 = (tid & 7) * 2;             // feature pair
    const int xdre = 2 * xr + ((xr & 16) >> 2);

    // ---- phase-1 weights (interleaved [k][u][g]) + biases ----
    for (int i = tid; i < 20480; i += THREADS) {
        int k = i >> 8, j = i & 255, u = j >> 2, g = j & 3, row = g * 64 + u;
        sh[WT + i] = (k < 16) ? Wih1[row * 16 + k] : Whh1[row * 64 + (k - 16)];
    }
    for (int i = tid; i < 12288; i += THREADS) {
        int k = i >> 7, j = i & 127, u = j >> 2, g = j & 3, row = g * 32 + u;
        sh[W2o + i] = (k < 64) ? Wih2[row * 64 + k] : Whh2[row * 32 + (k - 64)];
    }
    if (tid < 256) { int u = tid >> 2, g = tid & 3; sh[B1o + tid] = b1[g * 64 + u]; }
    if (tid < 128) { int u = tid >> 2, g = tid & 3; sh[B2o + tid] = b2[g * 32 + u]; }
    if (tid < 128) { int u = tid >> 2, g = tid & 3; sh[B3o + tid] = b3[g * 32 + u]; }
    if (tid < 256) { int u = tid >> 2, g = tid & 3; sh[B4o + tid] = b4[g * 64 + u]; }
    if (tid < 16)  sh[BOo + tid] = bout[tid];
    for (int i = tid; i < 4352; i += THREADS) sh[H1o + i] = 0.f;   // h1 buf0
    for (int i = tid; i < 2176; i += THREADS) sh[H2o + i] = 0.f;   // h2 buf0
    {   // x(0) -> XIN buf0, dup pairs
        float2 gx = *reinterpret_cast<const float2*>(x + (row0 + xr) * (TT * 16) + xf0);
        *reinterpret_cast<ull*>(sh + XINo + (xf0    ) * RS + xdre) = pack2(gx.x, gx.x);
        *reinterpret_cast<ull*>(sh + XINo + (xf0 + 1) * RS + xdre) = pack2(gx.y, gx.y);
    }
    __syncthreads();

    // bias gate-pair packs (direct ulonglong2 from interleaved bias arrays)
    ull b1p[2][2], b2p[1][2];
#pragma unroll
    for (int j = 0; j < 2; j++) {
        ulonglong2 bb = *reinterpret_cast<const ulonglong2*>(sh + B1o + (u0a + j) * 4);
        b1p[j][0] = bb.x; b1p[j][1] = bb.y;
    }
    {
        ulonglong2 bb = *reinterpret_cast<const ulonglong2*>(sh + B2o + u0b * 4);
        b2p[0][0] = bb.x; b2p[0][1] = bb.y;
    }

    float c1[2][4], c2[1][4];
#pragma unroll
    for (int j = 0; j < 2; j++)
#pragma unroll
        for (int q = 0; q < 4; q++) c1[j][q] = 0.f;
#pragma unroll
    for (int q = 0; q < 4; q++) c2[0][q] = 0.f;

    // ---- phase 1: encoder. accL1 enters each t as b1 + Whh1@h1(t-1). ----
    ull accL1[2][2][4], accL2[1][2][4];
    init_acc<2>(accL1, b1p);

    for (int t = 0; t < TT; t++) {
        const int p = t & 1;
        float2 gx;
        const bool pf = (t + 1 < TT);
        if (pf) gx = *reinterpret_cast<const float2*>(
            x + (row0 + xr) * (TT * 16) + (t + 1) * 16 + xf0);
        accum<2, 256>(sh + XINo + p * (16 * RS), sh + WT + u0a * 4, 16, accL1, doff0);
        if (pf) {
            float* xb = sh + XINo + (p ^ 1) * (16 * RS);
            *reinterpret_cast<ull*>(xb + (xf0    ) * RS + xdre) = pack2(gx.x, gx.x);
            *reinterpret_cast<ull*>(xb + (xf0 + 1) * RS + xdre) = pack2(gx.y, gx.y);
        }
        if (grpA) {
            act_store<2>(accL1, c1, sh + H1o + (p ^ 1) * (64 * RS) + u0a * RS, doff0);
            init_acc<1>(accL2, b2p);
            accum<1, 128>(sh + H2o + p * (32 * RS), sh + W2o + 64 * 128 + u0b * 4, 32, accL2, doff0);
        } else {
            init_acc<1>(accL2, b2p);
            accum<1, 128>(sh + H2o + p * (32 * RS), sh + W2o + 64 * 128 + u0b * 4, 32, accL2, doff0);
            act_store<2>(accL1, c1, sh + H1o + (p ^ 1) * (64 * RS) + u0a * RS, doff0);
        }
        __syncthreads();
        accum<1, 128>(sh + H1o + (p ^ 1) * (64 * RS), sh + W2o + u0b * 4, 64, accL2, doff0);
        if (grpA) {
            act_store<1>(accL2, c2, sh + H2o + (p ^ 1) * (32 * RS) + u0b * RS, doff0);
            init_acc<2>(accL1, b1p);
            accum<2, 256>(sh + H1o + (p ^ 1) * (64 * RS), sh + WT + 16 * 256 + u0a * 4, 64, accL1, doff0);
        } else {
            init_acc<2>(accL1, b1p);
            accum<2, 256>(sh + H1o + (p ^ 1) * (64 * RS), sh + WT + 16 * 256 + u0a * 4, 64, accL1, doff0);
            act_store<1>(accL2, c2, sh + H2o + (p ^ 1) * (32 * RS) + u0b * RS, doff0);
        }
        __syncthreads();
    }
    // latent = h2(29) in H2 buf 0

    // ---- phase-2 weights ----
    for (int i = tid; i < 4096; i += THREADS) {
        int k = i >> 7, j = i & 127, u = j >> 2, g = j & 3, row = g * 32 + u;
        sh[WT + i] = Whh3[row * 32 + k];
    }
    for (int i = tid; i < 24576; i += THREADS) {
        int k = i >> 8, j = i & 255, u = j >> 2, g = j & 3, row = g * 64 + u;
        sh[W4o + i] = (k < 32) ? Wih4[row * 32 + k] : Whh4[row * 64 + (k - 32)];
    }
    for (int i = tid; i < 1024; i += THREADS) {
        int jr = i >> 4, f = i & 15;
        sh[WOUTo + i] = Wout[f * 64 + jr];
    }
    for (int i = tid; i < 4096; i += THREADS) {
        int k = i >> 7, j = i & 127, u = j >> 2, g = j & 3, row = g * 32 + u;
        sh[WIH3o + i] = Wih3[row * 32 + k];
    }
    __syncthreads();

    // zin3 = Wih3 @ latent + b3 (constant over t), in registers
    ull zin3[1][2][4];
    {
        ull b3p[1][2];
        ulonglong2 bb = *reinterpret_cast<const ulonglong2*>(sh + B3o + u0b * 4);
        b3p[0][0] = bb.x; b3p[0][1] = bb.y;
        init_acc<1>(zin3, b3p);
        accum<1, 128>(sh + H2o, sh + WIH3o + u0b * 4, 32, zin3, doff0);
        __syncthreads();
        for (int i = tid; i < 2176; i += THREADS) sh[H2o + i] = 0.f;  // h3 buf0
        for (int i = tid; i < 4352; i += THREADS) sh[H1o + i] = 0.f;  // h4 buf0
    }
    __syncthreads();

    ull b4p[2][2];
#pragma unroll
    for (int j = 0; j < 2; j++) {
        ulonglong2 bb = *reinterpret_cast<const ulonglong2*>(sh + B4o + (u0a + j) * 4);
        b4p[j][0] = bb.x; b4p[j][1] = bb.y;
    }
    const ull boutp = *reinterpret_cast<const ull*>(sh + BOo + xf0);

    float c3[1][4], c4[2][4];
#pragma unroll
    for (int q = 0; q < 4; q++) c3[0][q] = 0.f;
#pragma unroll
    for (int j = 0; j < 2; j++)
#pragma unroll
        for (int q = 0; q < 4; q++) c4[j][q] = 0.f;

    // ---- phase 2: decoder. accL3 enters each t as zin3 + Whh3@h3(t-1). ----
    ull accL3[1][2][4], accL4[2][2][4];
#pragma unroll
    for (int g = 0; g < 2; g++)
#pragma unroll
        for (int pp = 0; pp < 4; pp++) accL3[0][g][pp] = zin3[0][g][pp];

    for (int t = 0; t < TT; t++) {
        const int p = t & 1;
        if (grpA) {
            act_store<1>(accL3, c3, sh + H2o + (p ^ 1) * (32 * RS) + u0b * RS, doff0);
            init_acc<2>(accL4, b4p);
            accum<2, 256>(sh + H1o + p * (64 * RS), sh + W4o + 32 * 256 + u0a * 4, 64, accL4, doff0);
        } else {
            init_acc<2>(accL4, b4p);
            accum<2, 256>(sh + H1o + p * (64 * RS), sh + W4o + 32 * 256 + u0a * 4, 64, accL4, doff0);
        }
        if (t > 0) {   // projection of h4(t-1): f-pairs packed, h4 dup broadcast
            const float* h4 = sh + H1o + p * (64 * RS);
            ull a0 = boutp;
#pragma unroll 8
            for (int j = 0; j < 64; j++) {
                ull w  = *reinterpret_cast<const ull*>(sh + WOUTo + j * 16 + xf0);
                ull hd = *reinterpret_cast<const ull*>(h4 + j * RS + xdre);
                ffma2(a0, w, hd);
            }
            float2 y = unpack2(a0);
            *reinterpret_cast<float2*>(out + (row0 + xr) * (TT * 16) + (t - 1) * 16 + xf0) = y;
        }
        if (!grpA)
            act_store<1>(accL3, c3, sh + H2o + (p ^ 1) * (32 * RS) + u0b * RS, doff0);
        __syncthreads();
        accum<2, 256>(sh + H2o + (p ^ 1) * (32 * RS), sh + W4o + u0a * 4, 32, accL4, doff0);
        if (grpA) {
            act_store<2>(accL4, c4, sh + H1o + (p ^ 1) * (64 * RS) + u0a * RS, doff0);
#pragma unroll
            for (int g = 0; g < 2; g++)
#pragma unroll
                for (int pp = 0; pp < 4; pp++) accL3[0][g][pp] = zin3[0][g][pp];
            accum<1, 128>(sh + H2o + (p ^ 1) * (32 * RS), sh + WT + u0b * 4, 32, accL3, doff0);
        } else {
#pragma unroll
            for (int g = 0; g < 2; g++)
#pragma unroll
                for (int pp = 0; pp < 4; pp++) accL3[0][g][pp] = zin3[0][g][pp];
            accum<1, 128>(sh + H2o + (p ^ 1) * (32 * RS), sh + WT + u0b * 4, 32, accL3, doff0);
            act_store<2>(accL4, c4, sh + H1o + (p ^ 1) * (64 * RS) + u0a * RS, doff0);
        }
        __syncthreads();
    }
    // final projection: h4(29) in H1 buf 0
    {
        const float* h4 = sh + H1o;
        ull a0 = boutp;
#pragma unroll 8
        for (int j = 0; j < 64; j++) {
            ull w  = *reinterpret_cast<const ull*>(sh + WOUTo + j * 16 + xf0);
            ull hd = *reinterpret_cast<const ull*>(h4 + j * RS + xdre);
            ffma2(a0, w, hd);
        }
        float2 y = unpack2(a0);
        *reinterpret_cast<float2*>(out + (row0 + xr) * (TT * 16) + (TT - 1) * 16 + xf0) = y;
    }
}

extern "C" void kernel_launch(void* const* d_in, const int* in_sizes, int n_in,
                              void* d_out, int out_size)
{
    const float* x    = (const float*)d_in[0];
    const float* Wih1 = (const float*)d_in[1];
    const float* Whh1 = (const float*)d_in[2];
    const float* b1   = (const float*)d_in[3];
    const float* Wih2 = (const float*)d_in[4];
    const float* Whh2 = (const float*)d_in[5];
    const float* b2   = (const float*)d_in[6];
    const float* Wih3 = (const float*)d_in[7];
    const float* Whh3 = (const float*)d_in[8];
    const float* b3   = (const float*)d_in[9];
    const float* Wih4 = (const float*)d_in[10];
    const float* Whh4 = (const float*)d_in[11];
    const float* b4   = (const float*)d_in[12];
    const float* Wout = (const float*)d_in[13];
    const float* bout = (const float*)d_in[14];
    float* out = (float*)d_out;

    cudaFuncSetAttribute(lstm_ae, cudaFuncAttributeMaxDynamicSharedMemorySize,
                         SHF * (int)sizeof(float));
    lstm_ae<<<256, THREADS, SHF * sizeof(float)>>>(
        x, Wih1, Whh1, b1, Wih2, Whh2, b2, Wih3, Whh3, b3,
        Wih4, Whh4, b4, Wout, bout, out);
}

// round 9
// speedup vs baseline: 1.0844x; 1.0844x over previous
#include <cuda_runtime.h>

#define THREADS 256
#define TT 30

typedef unsigned long long ull;

// ---------------- smem layout (float offsets) ----------------
// P1 weights (rows reordered to u*4+g, k-contiguous):
#define W1o 0        // [256][80]  = 20480
#define W2o 20480    // [128][96]  = 12288  (ends 32768)
// P2 overlay:
#define W3o 0        // [128][32]  = 4096
#define W4o 4096     // [256][96]  = 24576
#define WI3o 28672   // [128][32]  = 4096
#define WOo 32768    // [16][68]   = 1088   (ends 33856)
// biases (interleaved [u][g]):
#define B1o 33856
#define B2o 34112
#define B3o 34240
#define B4o 34368
#define BOo 34624    // 16 (ends 34640)
// state [row][k], k-contiguous, XOR-chunk swizzled, double buffered:
#define XINo 34640   // 2*[32][16] = 1024
#define H1o  35664   // 2*[32][64] = 4096   (P2: h4)
#define H2o  39760   // 2*[32][32] = 2048   (P2: h3)
#define SHF  41808   // 167232 bytes

__device__ __forceinline__ void ffma2(ull &acc, ull a, ull b){
    asm("fma.rn.f32x2 %0, %1, %2, %0;" : "+l"(acc) : "l"(a), "l"(b));
}
__device__ __forceinline__ ull pack2(float x, float y){
    ull r; asm("mov.b64 %0, {%1, %2};" : "=l"(r) : "f"(x), "f"(y)); return r;
}
__device__ __forceinline__ float2 unpack2(ull v){
    float2 f; asm("mov.b64 {%0, %1}, %2;" : "=f"(f.x), "=f"(f.y) : "l"(v)); return f;
}
__device__ __forceinline__ float ex2x(float x){
    float e; asm("ex2.approx.f32 %0, %1;" : "=f"(e) : "f"(x)); return e;
}
__device__ __forceinline__ float rcpx(float x){
    float r; asm("rcp.approx.f32 %0, %1;" : "=f"(r) : "f"(x)); return r;
}

// 8-MUFU LSTM activation (gate order i,f,g,o). Returns h, updates c.
__device__ __forceinline__ float act8(float zi, float zf, float zg, float zo, float &c){
    const float K1 = -1.4426950408889634f;
    float ei = ex2x(K1 * zi);
    float ef = ex2x(K1 * zf);
    float eg = ex2x(2.0f * K1 * zg);
    float eo = ex2x(K1 * zo);
    float A = 1.0f + ei, F = 1.0f + ef, G = 1.0f + eg, O = 1.0f + eo;
    float it = (1.0f - eg) * rcpx(A * G);
    float cn = fmaf(c, rcpx(F), it);
    float ec = ex2x(2.0f * K1 * cn);
    float C = 1.0f + ec;
    c = cn;
    return (1.0f - ec) * rcpx(O * C);
}

// k-pair packed accumulation.
// acc[j][g][i] is an f32x2 accumulating k-pairs for unit u0+j, gate g, row r0+i.
// inb: state base pre-offset by r0*ST; chunks XOR-swizzled by s (the rows' r>>2).
// Wb:  weight base pre-offset to row (u0*4), stride WST, k-contiguous (no swizzle).
template<int NU, int NKQ>
__device__ __forceinline__ void accum(const float* __restrict__ inb, int ST, int s,
                                      const float* __restrict__ Wb, int WST,
                                      ull (&acc)[NU][4][4])
{
#pragma unroll 4
    for (int kq = 0; kq < NKQ; kq++) {
        const float* ib = inb + 4 * (kq ^ s);
        ulonglong2 h0 = *reinterpret_cast<const ulonglong2*>(ib);
        ulonglong2 h1 = *reinterpret_cast<const ulonglong2*>(ib + ST);
        ulonglong2 h2 = *reinterpret_cast<const ulonglong2*>(ib + 2 * ST);
        ulonglong2 h3 = *reinterpret_cast<const ulonglong2*>(ib + 3 * ST);
#pragma unroll
        for (int j = 0; j < NU; j++)
#pragma unroll
            for (int g = 0; g < 4; g++) {
                ulonglong2 wv = *reinterpret_cast<const ulonglong2*>(Wb + (j*4+g)*WST + 4*kq);
                ffma2(acc[j][g][0], wv.x, h0.x); ffma2(acc[j][g][0], wv.y, h0.y);
                ffma2(acc[j][g][1], wv.x, h1.x); ffma2(acc[j][g][1], wv.y, h1.y);
                ffma2(acc[j][g][2], wv.x, h2.x); ffma2(acc[j][g][2], wv.y, h2.y);
                ffma2(acc[j][g][3], wv.x, h3.x); ffma2(acc[j][g][3], wv.y, h3.y);
            }
    }
}

template<int NU>
__device__ __forceinline__ void init_acc(ull (&acc)[NU][4][4], const float (&b)[NU][4]){
#pragma unroll
    for (int j = 0; j < NU; j++)
#pragma unroll
        for (int g = 0; g < 4; g++) {
            ull bp = pack2(b[j][g], 0.0f);
#pragma unroll
            for (int i = 0; i < 4; i++) acc[j][g][i] = bp;
        }
}

// fold k-pairs (lo+hi), activate, store h scalars into [row][k=unit] swizzled layout.
// hb pre-offset by r0*ST; s = rows' swizzle.
template<int NU>
__device__ __forceinline__ void act_store(ull (&acc)[NU][4][4], float (&c)[NU][4],
                                          float* hb, int ST, int s, int u0)
{
#pragma unroll
    for (int j = 0; j < NU; j++) {
        int u = u0 + j;
        float* col = hb + 4 * ((u >> 2) ^ s) + (u & 3);
#pragma unroll
        for (int i = 0; i < 4; i++) {
            float2 a0 = unpack2(acc[j][0][i]);
            float2 a1 = unpack2(acc[j][1][i]);
            float2 a2 = unpack2(acc[j][2][i]);
            float2 a3 = unpack2(acc[j][3][i]);
            float h = act8(a0.x + a0.y, a1.x + a1.y, a2.x + a2.y, a3.x + a3.y, c[j][i]);
            col[i * ST] = h;
        }
    }
}

__global__ void __launch_bounds__(THREADS, 1)
lstm_ae(const float* __restrict__ x,
        const float* __restrict__ Wih1, const float* __restrict__ Whh1, const float* __restrict__ b1,
        const float* __restrict__ Wih2, const float* __restrict__ Whh2, const float* __restrict__ b2,
        const float* __restrict__ Wih3, const float* __restrict__ Whh3, const float* __restrict__ b3,
        const float* __restrict__ Wih4, const float* __restrict__ Whh4, const float* __restrict__ b4,
        const float* __restrict__ Wout, const float* __restrict__ bout,
        float* __restrict__ out)
{
    extern __shared__ float sh[];
    const int tid = threadIdx.x;
    const long row0 = (long)blockIdx.x * 32;

    const int ug  = tid >> 3;              // 0..31
    const int r0  = (tid & 7) * 4;         // 4 rows per thread
    const int sw  = tid & 7;               // = r>>2 for all 4 rows
    const int swx = sw & 3;                // XIN (4 chunks)
    const int u0a = ug * 2;                // H=64 layers: 2 units
    const int u0b = ug;                    // H=32 layers: 1 unit

    // projection / x-io mapping: 1 row, features f and f+8
    const int xr = tid >> 3;
    const int xf = tid & 7;
    const int sxw = (xr >> 2) & 3;         // XIN writer swizzle
    const int sp  = (xr >> 2) & 7;         // h4 reader swizzle

    // ---- P1 weights (rows u*4+g, k-contiguous) + biases ----
    for (int i = tid; i < 256 * 80; i += THREADS) {
        int row = i / 80, k = i - row * 80;
        int u = row >> 2, g = row & 3;
        sh[W1o + i] = (k < 16) ? Wih1[(g * 64 + u) * 16 + k]
                               : Whh1[(g * 64 + u) * 64 + (k - 16)];
    }
    for (int i = tid; i < 128 * 96; i += THREADS) {
        int row = i / 96, k = i - row * 96;
        int u = row >> 2, g = row & 3;
        sh[W2o + i] = (k < 64) ? Wih2[(g * 32 + u) * 64 + k]
                               : Whh2[(g * 32 + u) * 32 + (k - 64)];
    }
    if (tid < 256) { int u = tid >> 2, g = tid & 3; sh[B1o + tid] = b1[g * 64 + u]; }
    if (tid < 128) { int u = tid >> 2, g = tid & 3; sh[B2o + tid] = b2[g * 32 + u]; }
    if (tid < 128) { int u = tid >> 2, g = tid & 3; sh[B3o + tid] = b3[g * 32 + u]; }
    if (tid < 256) { int u = tid >> 2, g = tid & 3; sh[B4o + tid] = b4[g * 64 + u]; }
    if (tid < 16)  sh[BOo + tid] = bout[tid];
    for (int i = tid; i < 2048; i += THREADS) sh[H1o + i] = 0.f;  // h1 buf0
    for (int i = tid; i < 1024; i += THREADS) sh[H2o + i] = 0.f;  // h2 buf0
    {   // x(0) -> XIN buf0
        int xf0 = xf * 2;
        float2 gx = *reinterpret_cast<const float2*>(x + (row0 + xr) * (TT * 16) + xf0);
        float* dst = sh + XINo + xr * 16 + 4 * ((xf0 >> 2) ^ sxw) + (xf0 & 3);
        *reinterpret_cast<float2*>(dst) = gx;
    }
    __syncthreads();

    float bs1[2][4], bs2[1][4];
#pragma unroll
    for (int j = 0; j < 2; j++)
#pragma unroll
        for (int g = 0; g < 4; g++) bs1[j][g] = sh[B1o + (u0a + j) * 4 + g];
#pragma unroll
    for (int g = 0; g < 4; g++) bs2[0][g] = sh[B2o + u0b * 4 + g];

    float c1[2][4], c2[1][4];
#pragma unroll
    for (int j = 0; j < 2; j++)
#pragma unroll
        for (int i = 0; i < 4; i++) c1[j][i] = 0.f;
#pragma unroll
    for (int i = 0; i < 4; i++) c2[0][i] = 0.f;

    // ---- phase 1: encoder LSTM(64) -> LSTM(32) ----
    for (int t = 0; t < TT; t++) {
        const int p = t & 1;
        float2 gx;
        const bool pf = (t + 1 < TT);
        if (pf) gx = *reinterpret_cast<const float2*>(
            x + (row0 + xr) * (TT * 16) + (t + 1) * 16 + xf * 2);
        {   // L1
            ull a1[2][4][4];
            init_acc<2>(a1, bs1);
            accum<2, 4>(sh + XINo + p * 512 + r0 * 16, 16, swx,
                        sh + W1o + (u0a * 4) * 80, 80, a1);
            accum<2, 16>(sh + H1o + p * 2048 + r0 * 64, 64, sw,
                         sh + W1o + (u0a * 4) * 80 + 16, 80, a1);
            if (pf) {
                int xf0 = xf * 2;
                float* dst = sh + XINo + (p ^ 1) * 512 + xr * 16
                           + 4 * ((xf0 >> 2) ^ sxw) + (xf0 & 3);
                *reinterpret_cast<float2*>(dst) = gx;
            }
            act_store<2>(a1, c1, sh + H1o + (p ^ 1) * 2048 + r0 * 64, 64, sw, u0a);
        }
        __syncthreads();
        {   // L2
            ull a2[1][4][4];
            init_acc<1>(a2, bs2);
            accum<1, 16>(sh + H1o + (p ^ 1) * 2048 + r0 * 64, 64, sw,
                         sh + W2o + (u0b * 4) * 96, 96, a2);
            accum<1, 8>(sh + H2o + p * 1024 + r0 * 32, 32, sw,
                        sh + W2o + (u0b * 4) * 96 + 64, 96, a2);
            act_store<1>(a2, c2, sh + H2o + (p ^ 1) * 1024 + r0 * 32, 32, sw, u0b);
        }
        __syncthreads();
    }
    // latent = h2(29) in H2 buf 0

    // ---- P2 weights (overlay) ----
    for (int i = tid; i < 128 * 32; i += THREADS) {
        int row = i >> 5, k = i & 31;
        int u = row >> 2, g = row & 3;
        sh[W3o + i] = Whh3[(g * 32 + u) * 32 + k];
    }
    for (int i = tid; i < 256 * 96; i += THREADS) {
        int row = i / 96, k = i - row * 96;
        int u = row >> 2, g = row & 3;
        sh[W4o + i] = (k < 32) ? Wih4[(g * 64 + u) * 32 + k]
                               : Whh4[(g * 64 + u) * 64 + (k - 32)];
    }
    for (int i = tid; i < 128 * 32; i += THREADS) {
        int row = i >> 5, k = i & 31;
        int u = row >> 2, g = row & 3;
        sh[WI3o + i] = Wih3[(g * 32 + u) * 32 + k];
    }
    for (int i = tid; i < 16 * 68; i += THREADS) {
        int f = i / 68, j = i - f * 68;
        sh[WOo + i] = (j < 64) ? Wout[f * 64 + j] : 0.f;
    }
    __syncthreads();

    // zin3 = Wih3 @ latent + b3 (constant over t), in registers
    ull z3[1][4][4];
    {
        float bs3[1][4];
#pragma unroll
        for (int g = 0; g < 4; g++) bs3[0][g] = sh[B3o + u0b * 4 + g];
        init_acc<1>(z3, bs3);
        accum<1, 8>(sh + H2o + r0 * 32, 32, sw, sh + WI3o + (u0b * 4) * 32, 32, z3);
    }
    __syncthreads();
    for (int i = tid; i < 1024; i += THREADS) sh[H2o + i] = 0.f;  // h3 buf0
    for (int i = tid; i < 2048; i += THREADS) sh[H1o + i] = 0.f;  // h4 buf0
    __syncthreads();

    float bs4[2][4];
#pragma unroll
    for (int j = 0; j < 2; j++)
#pragma unroll
        for (int g = 0; g < 4; g++) bs4[j][g] = sh[B4o + (u0a + j) * 4 + g];
    const ull bo1 = pack2(sh[BOo + xf], 0.0f);
    const ull bo2 = pack2(sh[BOo + xf + 8], 0.0f);

    float c3[1][4], c4[2][4];
#pragma unroll
    for (int i = 0; i < 4; i++) c3[0][i] = 0.f;
#pragma unroll
    for (int j = 0; j < 2; j++)
#pragma unroll
        for (int i = 0; i < 4; i++) c4[j][i] = 0.f;

    // ---- phase 2: decoder LSTM(32) -> LSTM(64) -> projection ----
    for (int t = 0; t < TT; t++) {
        const int p = t & 1;
        if (t > 0) {   // projection of h4(t-1) from H1[p]
            const float* hb = sh + H1o + p * 2048 + xr * 64;
            ull a0 = bo1, a1 = bo2;
#pragma unroll 4
            for (int kq = 0; kq < 16; kq++) {
                ulonglong2 hv = *reinterpret_cast<const ulonglong2*>(hb + 4 * (kq ^ sp));
                ulonglong2 w0 = *reinterpret_cast<const ulonglong2*>(sh + WOo + xf * 68 + 4 * kq);
                ulonglong2 w1 = *reinterpret_cast<const ulonglong2*>(sh + WOo + (xf + 8) * 68 + 4 * kq);
                ffma2(a0, w0.x, hv.x); ffma2(a0, w0.y, hv.y);
                ffma2(a1, w1.x, hv.x); ffma2(a1, w1.y, hv.y);
            }
            float2 y0 = unpack2(a0), y1 = unpack2(a1);
            float* op = out + (row0 + xr) * (TT * 16) + (t - 1) * 16;
            op[xf]     = y0.x + y0.y;
            op[xf + 8] = y1.x + y1.y;
        }
        {   // L3 (ih-part constant, lives in z3)
            ull a3[1][4][4];
#pragma unroll
            for (int g = 0; g < 4; g++)
#pragma unroll
                for (int i = 0; i < 4; i++) a3[0][g][i] = z3[0][g][i];
            accum<1, 8>(sh + H2o + p * 1024 + r0 * 32, 32, sw,
                        sh + W3o + (u0b * 4) * 32, 32, a3);
            act_store<1>(a3, c3, sh + H2o + (p ^ 1) * 1024 + r0 * 32, 32, sw, u0b);
        }
        __syncthreads();
        {   // L4
            ull a4[2][4][4];
            init_acc<2>(a4, bs4);
            accum<2, 8>(sh + H2o + (p ^ 1) * 1024 + r0 * 32, 32, sw,
                        sh + W4o + (u0a * 4) * 96, 96, a4);
            accum<2, 16>(sh + H1o + p * 2048 + r0 * 64, 64, sw,
                         sh + W4o + (u0a * 4) * 96 + 32, 96, a4);
            act_store<2>(a4, c4, sh + H1o + (p ^ 1) * 2048 + r0 * 64, 64, sw, u0a);
        }
        __syncthreads();
    }
    // final projection: h4(29) in H1 buf 0
    {
        const float* hb = sh + H1o + xr * 64;
        ull a0 = bo1, a1 = bo2;
#pragma unroll 4
        for (int kq = 0; kq < 16; kq++) {
            ulonglong2 hv = *reinterpret_cast<const ulonglong2*>(hb + 4 * (kq ^ sp));
            ulonglong2 w0 = *reinterpret_cast<const ulonglong2*>(sh + WOo + xf * 68 + 4 * kq);
            ulonglong2 w1 = *reinterpret_cast<const ulonglong2*>(sh + WOo + (xf + 8) * 68 + 4 * kq);
            ffma2(a0, w0.x, hv.x); ffma2(a0, w0.y, hv.y);
            ffma2(a1, w1.x, hv.x); ffma2(a1, w1.y, hv.y);
        }
        float2 y0 = unpack2(a0), y1 = unpack2(a1);
        float* op = out + (row0 + xr) * (TT * 16) + (TT - 1) * 16;
        op[xf]     = y0.x + y0.y;
        op[xf + 8] = y1.x + y1.y;
    }
}

extern "C" void kernel_launch(void* const* d_in, const int* in_sizes, int n_in,
                              void* d_out, int out_size)
{
    const float* x    = (const float*)d_in[0];
    const float* Wih1 = (const float*)d_in[1];
    const float* Whh1 = (const float*)d_in[2];
    const float* b1   = (const float*)d_in[3];
    const float* Wih2 = (const float*)d_in[4];
    const float* Whh2 = (const float*)d_in[5];
    const float* b2   = (const float*)d_in[6];
    const float* Wih3 = (const float*)d_in[7];
    const float* Whh3 = (const float*)d_in[8];
    const float* b3   = (const float*)d_in[9];
    const float* Wih4 = (const float*)d_in[10];
    const float* Whh4 = (const float*)d_in[11];
    const float* b4   = (const float*)d_in[12];
    const float* Wout = (const float*)d_in[13];
    const float* bout = (const float*)d_in[14];
    float* out = (float*)d_out;

    cudaFuncSetAttribute(lstm_ae, cudaFuncAttributeMaxDynamicSharedMemorySize,
                         SHF * (int)sizeof(float));
    lstm_ae<<<256, THREADS, SHF * sizeof(float)>>>(
        x, Wih1, Whh1, b1, Wih2, Whh2, b2, Wih3, Whh3, b3,
        Wih4, Whh4, b4, Wout, bout, out);
}